// round 6
// baseline (speedup 1.0000x reference)
#include <cuda_runtime.h>
#include <math.h>

// ---------------- problem constants ----------------
#define BQ   16
#define NPTS 4096
#define MTOT (BQ*NPTS)          // 65536 points
#define FW   56                 // fmap H=W
#define PS   8

// ---------------- scratch (device globals; no allocation) ----------------
__device__ float d_pe   [MTOT*48];          // positional embedding
__device__ float d_pf1  [MTOT*256];         // after MLP layer 1 (gelu)
__device__ float d_fused[MTOT*576];         // [pf(256) | patches(256) | gc(64)]
__device__ float d_h    [MTOT*512];         // head hidden (gelu)
__device__ float d_f1   [BQ*16*112*112];    // plane conv1
__device__ float d_f2   [BQ*32*56*56];      // plane conv2
__device__ float d_fmap [BQ*4*56*56];       // plane conv3
__device__ float d_g1   [BQ*4*112*112];
__device__ float d_g2   [BQ*8*56*56];
__device__ float d_g3   [BQ*16*28*28];
__device__ float d_g4   [BQ*32*14*14];
__device__ float d_g5   [BQ*64*7*7];
__device__ float d_gc   [BQ*64];

// ---------------- helpers ----------------
__device__ __forceinline__ float gelu_tanh(float x) {
    const float c0 = 0.7978845608028654f;   // sqrt(2/pi)
    float x3 = x * x * x;
    float t  = tanhf(c0 * (x + 0.044715f * x3));
    return 0.5f * x * (1.0f + t);
}

// ---------------- positional embedding ----------------
// pe[pt, i*4 + {0,1,2,3}] = sin(2^i x), sin(2^i y), cos(2^i x), cos(2^i y)
__global__ void embed_kernel(const float* __restrict__ points, float* __restrict__ pe) {
    int idx = blockIdx.x * blockDim.x + threadIdx.x;   // over MTOT*12
    if (idx >= MTOT * 12) return;
    int pt = idx / 12, i = idx % 12;
    float x = points[pt * 2 + 0];
    float y = points[pt * 2 + 1];
    float f = exp2f((float)i);
    float sx, cx, sy, cy;
    sincosf(f * x, &sx, &cx);
    sincosf(f * y, &sy, &cy);
    float4 v = make_float4(sx, sy, cx, cy);
    ((float4*)pe)[pt * 12 + i] = v;
}

// ---------------- direct 3x3 conv + gelu ----------------
__global__ void conv3x3_gelu(const float* __restrict__ in, const float* __restrict__ wt,
                             const float* __restrict__ bias, float* __restrict__ out,
                             int Cin, int Cout, int Hin, int Win, int Hout, int Wout,
                             int stride, int total) {
    int idx = blockIdx.x * blockDim.x + threadIdx.x;
    if (idx >= total) return;
    int ox = idx % Wout; int t = idx / Wout;
    int oy = t % Hout;   t /= Hout;
    int co = t % Cout;   int b = t / Cout;

    float acc = bias[co];
    const float* wp = wt + co * Cin * 9;
    int iy0 = oy * stride - 1;
    int ix0 = ox * stride - 1;
    for (int ci = 0; ci < Cin; ci++) {
        const float* ip = in + ((size_t)(b * Cin + ci) * Hin) * Win;
        const float* wc = wp + ci * 9;
        #pragma unroll
        for (int ky = 0; ky < 3; ky++) {
            int iy = iy0 + ky;
            if (iy < 0 || iy >= Hin) continue;
            const float* irow = ip + (size_t)iy * Win;
            #pragma unroll
            for (int kx = 0; kx < 3; kx++) {
                int ix = ix0 + kx;
                if (ix < 0 || ix >= Win) continue;
                acc += irow[ix] * wc[ky * 3 + kx];
            }
        }
    }
    out[idx] = gelu_tanh(acc);
}

// ---------------- global mean over 7x7 ----------------
__global__ void gmean_kernel(const float* __restrict__ g5, float* __restrict__ gc) {
    int idx = blockIdx.x * blockDim.x + threadIdx.x;   // BQ*64
    if (idx >= BQ * 64) return;
    const float* p = g5 + (size_t)idx * 49;
    float s = 0.f;
    #pragma unroll
    for (int i = 0; i < 49; i++) s += p[i];
    gc[idx] = s / 49.0f;
}

// ---------------- bilinear patch gather + gc broadcast into fused ----------------
// 256 threads = 4 points x 64 (i,j) positions
__global__ void patch_kernel(const float* __restrict__ points, const float* __restrict__ fmap,
                             const float* __restrict__ gc, float* __restrict__ fused) {
    int p = blockIdx.x * 4 + (threadIdx.x >> 6);
    int t = threadIdx.x & 63;
    int b = p >> 12;   // p / 4096
    float px = points[p * 2 + 0];
    float py = points[p * 2 + 1];
    int i = t >> 3, j = t & 7;

    const float step = 2.0f / 55.0f;
    float gx = (px * 2.0f - 1.0f) + ((float)i - 3.5f) * step;
    float gy = (py * 2.0f - 1.0f) + ((float)j - 3.5f) * step;
    float ix = (gx + 1.0f) * 0.5f * 55.0f;
    float iy = (gy + 1.0f) * 0.5f * 55.0f;
    float x0f = floorf(ix), y0f = floorf(iy);
    int x0 = (int)x0f, y0 = (int)y0f;
    int x1 = x0 + 1,  y1 = y0 + 1;
    float wx1 = ix - x0f, wx0 = 1.0f - wx1;
    float wy1 = iy - y0f, wy0 = 1.0f - wy1;

    bool vx0 = (x0 >= 0) && (x0 < FW), vx1 = (x1 >= 0) && (x1 < FW);
    bool vy0 = (y0 >= 0) && (y0 < FW), vy1 = (y1 >= 0) && (y1 < FW);
    int cx0 = min(max(x0, 0), FW - 1), cx1 = min(max(x1, 0), FW - 1);
    int cy0 = min(max(y0, 0), FW - 1), cy1 = min(max(y1, 0), FW - 1);
    float w00 = (vx0 && vy0) ? wx0 * wy0 : 0.f;
    float w10 = (vx1 && vy0) ? wx1 * wy0 : 0.f;
    float w01 = (vx0 && vy1) ? wx0 * wy1 : 0.f;
    float w11 = (vx1 && vy1) ? wx1 * wy1 : 0.f;
    int i00 = cy0 * FW + cx0, i10 = cy0 * FW + cx1;
    int i01 = cy1 * FW + cx0, i11 = cy1 * FW + cx1;

    float* orow = fused + (size_t)p * 576;
    #pragma unroll
    for (int c = 0; c < 4; c++) {
        const float* f = fmap + (size_t)(b * 4 + c) * (FW * FW);
        float v = w00 * f[i00] + w10 * f[i10] + w01 * f[i01] + w11 * f[i11];
        orow[256 + c * 64 + t] = v;
    }
    orow[512 + t] = gc[b * 64 + t];
}

// ---------------- tiled SGEMM-NT: C[m,n] = sum_k A[m,k]*W[n,k] + bias[n] ----------------
// BM=BN=128, BK=8, 256 threads, 8x8 per-thread tile, smem double buffered.
// Requires M%128==0, N%128==0, K%8==0. A: [M,K] rm. W: [N,K] rm.
template<bool DOGELU>
__global__ void __launch_bounds__(256) sgemm_nt(const float* __restrict__ A,
                                                const float* __restrict__ W,
                                                const float* __restrict__ bias,
                                                float* __restrict__ C,
                                                int K, int ldc) {
    __shared__ float As[2][8][128];
    __shared__ float Bs[2][8][128];
    const int bm = blockIdx.y << 7;
    const int bn = blockIdx.x << 7;
    const int tid = threadIdx.x;
    const int lrow = tid >> 1;
    const int lcol = (tid & 1) << 2;
    const float* Ap = A + (size_t)(bm + lrow) * K + lcol;
    const float* Wp = W + (size_t)(bn + lrow) * K + lcol;
    const int tx = tid & 15, ty = tid >> 4;

    float acc[8][8];
    #pragma unroll
    for (int i = 0; i < 8; i++)
        #pragma unroll
        for (int j = 0; j < 8; j++) acc[i][j] = 0.f;

    // preload tile 0
    {
        float4 a4 = *(const float4*)Ap;
        float4 b4 = *(const float4*)Wp;
        As[0][lcol + 0][lrow] = a4.x; As[0][lcol + 1][lrow] = a4.y;
        As[0][lcol + 2][lrow] = a4.z; As[0][lcol + 3][lrow] = a4.w;
        Bs[0][lcol + 0][lrow] = b4.x; Bs[0][lcol + 1][lrow] = b4.y;
        Bs[0][lcol + 2][lrow] = b4.z; Bs[0][lcol + 3][lrow] = b4.w;
    }

    const int nk = K >> 3;
    int cur = 0;
    for (int kt = 0; kt < nk; kt++) {
        __syncthreads();
        float4 a4n, b4n;
        bool more = (kt + 1 < nk);
        if (more) {
            a4n = *(const float4*)(Ap + ((kt + 1) << 3));
            b4n = *(const float4*)(Wp + ((kt + 1) << 3));
        }
        #pragma unroll
        for (int kk = 0; kk < 8; kk++) {
            float ar[8], br[8];
            *(float4*)&ar[0] = *(const float4*)&As[cur][kk][(ty << 3) + 0];
            *(float4*)&ar[4] = *(const float4*)&As[cur][kk][(ty << 3) + 4];
            *(float4*)&br[0] = *(const float4*)&Bs[cur][kk][(tx << 3) + 0];
            *(float4*)&br[4] = *(const float4*)&Bs[cur][kk][(tx << 3) + 4];
            #pragma unroll
            for (int i = 0; i < 8; i++)
                #pragma unroll
                for (int j = 0; j < 8; j++)
                    acc[i][j] += ar[i] * br[j];
        }
        if (more) {
            int nxt = cur ^ 1;
            As[nxt][lcol + 0][lrow] = a4n.x; As[nxt][lcol + 1][lrow] = a4n.y;
            As[nxt][lcol + 2][lrow] = a4n.z; As[nxt][lcol + 3][lrow] = a4n.w;
            Bs[nxt][lcol + 0][lrow] = b4n.x; Bs[nxt][lcol + 1][lrow] = b4n.y;
            Bs[nxt][lcol + 2][lrow] = b4n.z; Bs[nxt][lcol + 3][lrow] = b4n.w;
            cur = nxt;
        }
    }

    // epilogue: bias + optional gelu, float4 stores
    float bv[8];
    #pragma unroll
    for (int j = 0; j < 8; j++) bv[j] = bias[bn + (tx << 3) + j];
    #pragma unroll
    for (int i = 0; i < 8; i++) {
        int m = bm + (ty << 3) + i;
        float outr[8];
        #pragma unroll
        for (int j = 0; j < 8; j++) {
            float v = acc[i][j] + bv[j];
            outr[j] = DOGELU ? gelu_tanh(v) : v;
        }
        float* cp = C + (size_t)m * ldc + bn + (tx << 3);
        *(float4*)(cp + 0) = *(float4*)&outr[0];
        *(float4*)(cp + 4) = *(float4*)&outr[4];
    }
}

// ---------------- final GEMV: out[m] = dot(h[m,:512], hw2) + hb2 ----------------
__global__ void gemv_out(const float* __restrict__ h, const float* __restrict__ w2,
                         const float* __restrict__ b2, float* __restrict__ out) {
    int m = blockIdx.x * 8 + (threadIdx.x >> 5);
    int lane = threadIdx.x & 31;
    const float4* hp = (const float4*)(h + (size_t)m * 512);
    const float4* wp = (const float4*)w2;
    float s = 0.f;
    #pragma unroll
    for (int it = 0; it < 4; it++) {
        float4 a = hp[lane + it * 32];
        float4 b = wp[lane + it * 32];
        s += a.x * b.x + a.y * b.y + a.z * b.z + a.w * b.w;
    }
    #pragma unroll
    for (int o = 16; o > 0; o >>= 1) s += __shfl_xor_sync(0xFFFFFFFFu, s, o);
    if (lane == 0) out[m] = s + b2[0];
}

// ---------------- launch ----------------
extern "C" void kernel_launch(void* const* d_in, const int* in_sizes, int n_in,
                              void* d_out, int out_size) {
    const float* points = (const float*)d_in[0];
    const float* images = (const float*)d_in[1];
    const float* pw1 = (const float*)d_in[2];  const float* pb1 = (const float*)d_in[3];
    const float* pw2 = (const float*)d_in[4];  const float* pb2 = (const float*)d_in[5];
    const float* pw3 = (const float*)d_in[6];  const float* pb3 = (const float*)d_in[7];
    const float* gw1 = (const float*)d_in[8];  const float* gb1 = (const float*)d_in[9];
    const float* gw2 = (const float*)d_in[10]; const float* gb2 = (const float*)d_in[11];
    const float* gw3 = (const float*)d_in[12]; const float* gb3 = (const float*)d_in[13];
    const float* gw4 = (const float*)d_in[14]; const float* gb4 = (const float*)d_in[15];
    const float* gw5 = (const float*)d_in[16]; const float* gb5 = (const float*)d_in[17];
    const float* lw1 = (const float*)d_in[18]; const float* lb1 = (const float*)d_in[19];
    const float* lw2 = (const float*)d_in[20]; const float* lb2 = (const float*)d_in[21];
    const float* hw1 = (const float*)d_in[22]; const float* hb1 = (const float*)d_in[23];
    const float* hw2 = (const float*)d_in[24]; const float* hb2 = (const float*)d_in[25];
    float* out = (float*)d_out;

    float *pe, *pf1, *fused, *h, *f1, *f2, *fmap, *g1, *g2, *g3, *g4, *g5, *gc;
    cudaGetSymbolAddress((void**)&pe,    d_pe);
    cudaGetSymbolAddress((void**)&pf1,   d_pf1);
    cudaGetSymbolAddress((void**)&fused, d_fused);
    cudaGetSymbolAddress((void**)&h,     d_h);
    cudaGetSymbolAddress((void**)&f1,    d_f1);
    cudaGetSymbolAddress((void**)&f2,    d_f2);
    cudaGetSymbolAddress((void**)&fmap,  d_fmap);
    cudaGetSymbolAddress((void**)&g1,    d_g1);
    cudaGetSymbolAddress((void**)&g2,    d_g2);
    cudaGetSymbolAddress((void**)&g3,    d_g3);
    cudaGetSymbolAddress((void**)&g4,    d_g4);
    cudaGetSymbolAddress((void**)&g5,    d_g5);
    cudaGetSymbolAddress((void**)&gc,    d_gc);

    const int T = 256;
    auto blocks = [](int total) { return (total + 255) / 256; };

    // point embedding
    embed_kernel<<<blocks(MTOT * 12), T>>>(points, pe);

    // plane encoder
    int t1 = BQ * 16 * 112 * 112;
    conv3x3_gelu<<<blocks(t1), T>>>(images, pw1, pb1, f1, 3, 16, 224, 224, 112, 112, 2, t1);
    int t2 = BQ * 32 * 56 * 56;
    conv3x3_gelu<<<blocks(t2), T>>>(f1, pw2, pb2, f2, 16, 32, 112, 112, 56, 56, 2, t2);
    int t3 = BQ * 4 * 56 * 56;
    conv3x3_gelu<<<blocks(t3), T>>>(f2, pw3, pb3, fmap, 32, 4, 56, 56, 56, 56, 1, t3);

    // global encoder
    int u1 = BQ * 4 * 112 * 112;
    conv3x3_gelu<<<blocks(u1), T>>>(images, gw1, gb1, g1, 3, 4, 224, 224, 112, 112, 2, u1);
    int u2 = BQ * 8 * 56 * 56;
    conv3x3_gelu<<<blocks(u2), T>>>(g1, gw2, gb2, g2, 4, 8, 112, 112, 56, 56, 2, u2);
    int u3 = BQ * 16 * 28 * 28;
    conv3x3_gelu<<<blocks(u3), T>>>(g2, gw3, gb3, g3, 8, 16, 56, 56, 28, 28, 2, u3);
    int u4 = BQ * 32 * 14 * 14;
    conv3x3_gelu<<<blocks(u4), T>>>(g3, gw4, gb4, g4, 16, 32, 28, 28, 14, 14, 2, u4);
    int u5 = BQ * 64 * 7 * 7;
    conv3x3_gelu<<<blocks(u5), T>>>(g4, gw5, gb5, g5, 32, 64, 14, 14, 7, 7, 2, u5);
    gmean_kernel<<<blocks(BQ * 64), T>>>(g5, gc);

    // point MLP: pf1 = gelu(pe @ lw1^T + lb1); fused[:, :256] = pf1 @ lw2^T + lb2
    {
        dim3 g(256 / 128, MTOT / 128);
        sgemm_nt<true><<<g, 256>>>(pe, lw1, lb1, pf1, 48, 256);
        sgemm_nt<false><<<g, 256>>>(pf1, lw2, lb2, fused, 256, 576);
    }

    // patches + gc into fused[:, 256:576]
    patch_kernel<<<MTOT / 4, 256>>>(points, fmap, gc, fused);

    // head: h = gelu(fused @ hw1^T + hb1); out = h @ hw2^T + hb2
    {
        dim3 g(512 / 128, MTOT / 128);
        sgemm_nt<true><<<g, 256>>>(fused, hw1, hb1, h, 576, 512);
    }
    gemv_out<<<MTOT / 8, 256>>>(h, hw2, hb2, out);

    (void)in_sizes; (void)n_in; (void)out_size;
}

// round 9
// speedup vs baseline: 2.0097x; 2.0097x over previous
#include <cuda_runtime.h>
#include <math.h>
#include <stdint.h>

// ---------------- problem constants ----------------
#define BQ   16
#define NPTS 4096
#define MTOT (BQ*NPTS)          // 65536 points
#define FW   56                 // fmap H=W
#define PS   8

// ---------------- scratch (device globals; no allocation) ----------------
__device__ float d_pe   [MTOT*64];          // positional embedding, K padded 48->64 (tf32-rounded)
__device__ float d_lw1p [256*64];           // lw1 zero-padded to K=64 (tf32-rounded)
__device__ float d_lw2t [256*256];          // lw2 tf32-rounded
__device__ float d_hw1t [512*576];          // hw1 tf32-rounded
__device__ float d_pf1  [MTOT*256];         // after MLP layer 1 (gelu, tf32-rounded)
__device__ float d_fused[MTOT*576];         // [pf(256) | patches(256) | gc(64)] (tf32-rounded)
__device__ float d_h    [MTOT*512];         // head hidden (gelu, fp32)
__device__ float d_f1   [BQ*16*112*112];
__device__ float d_f2   [BQ*32*56*56];
__device__ float d_fmap [BQ*4*56*56];
__device__ float d_g1   [BQ*4*112*112];
__device__ float d_g2   [BQ*8*56*56];
__device__ float d_g3   [BQ*16*28*28];
__device__ float d_g4   [BQ*32*14*14];
__device__ float d_g5   [BQ*64*7*7];
__device__ float d_gc   [BQ*64];

// ---------------- helpers ----------------
__device__ __forceinline__ float gelu_tanh(float x) {
    const float c0 = 0.7978845608028654f;   // sqrt(2/pi)
    float x3 = x * x * x;
    float t  = tanhf(c0 * (x + 0.044715f * x3));
    return 0.5f * x * (1.0f + t);
}

// round-to-nearest tf32 (keeps value as fp32 with low mantissa bits cleared)
__device__ __forceinline__ float tf32r(float x) {
    float y;
    asm("cvt.rna.tf32.f32 %0, %1;" : "=f"(y) : "f"(x));
    return y;
}

__device__ __forceinline__ uint32_t smem_u32(const void* p) {
    uint32_t a;
    asm("{ .reg .u64 t; cvta.to.shared.u64 t, %1; cvt.u32.u64 %0, t; }" : "=r"(a) : "l"(p));
    return a;
}

__device__ __forceinline__ void mma_tf32(float* c, const float* a, const float* b) {
    asm volatile("mma.sync.aligned.m16n8k8.row.col.f32.tf32.tf32.f32 "
        "{%0,%1,%2,%3}, {%4,%5,%6,%7}, {%8,%9}, {%0,%1,%2,%3};"
        : "+f"(c[0]), "+f"(c[1]), "+f"(c[2]), "+f"(c[3])
        : "r"(__float_as_uint(a[0])), "r"(__float_as_uint(a[1])),
          "r"(__float_as_uint(a[2])), "r"(__float_as_uint(a[3])),
          "r"(__float_as_uint(b[0])), "r"(__float_as_uint(b[1])));
}

// ---------------- positional embedding (K padded to 64, tf32-rounded) ----------------
__global__ void embed_kernel(const float* __restrict__ points, float* __restrict__ pe) {
    int idx = blockIdx.x * blockDim.x + threadIdx.x;   // over MTOT*16
    if (idx >= MTOT * 16) return;
    int pt = idx >> 4, i = idx & 15;
    float4 v;
    if (i < 12) {
        float x = points[pt * 2 + 0];
        float y = points[pt * 2 + 1];
        float f = exp2f((float)i);
        float sx, cx, sy, cy;
        sincosf(f * x, &sx, &cx);
        sincosf(f * y, &sy, &cy);
        v = make_float4(tf32r(sx), tf32r(sy), tf32r(cx), tf32r(cy));
    } else {
        v = make_float4(0.f, 0.f, 0.f, 0.f);
    }
    ((float4*)pe)[pt * 16 + i] = v;
}

// pack lw1 [256,48] -> [256,64] zero padded, tf32-rounded
__global__ void pack_lw1(const float* __restrict__ lw1, float* __restrict__ out) {
    int idx = blockIdx.x * blockDim.x + threadIdx.x;   // 256*64
    if (idx >= 256 * 64) return;
    int n = idx >> 6, k = idx & 63;
    out[idx] = (k < 48) ? tf32r(lw1[n * 48 + k]) : 0.f;
}

// tf32-rounded copy for weight matrices
__global__ void round_copy(const float* __restrict__ in, float* __restrict__ out, int n) {
    int idx = blockIdx.x * blockDim.x + threadIdx.x;
    if (idx < n) out[idx] = tf32r(in[idx]);
}

// ---------------- direct 3x3 conv + gelu ----------------
__global__ void conv3x3_gelu(const float* __restrict__ in, const float* __restrict__ wt,
                             const float* __restrict__ bias, float* __restrict__ out,
                             int Cin, int Cout, int Hin, int Win, int Hout, int Wout,
                             int stride, int total) {
    int idx = blockIdx.x * blockDim.x + threadIdx.x;
    if (idx >= total) return;
    int ox = idx % Wout; int t = idx / Wout;
    int oy = t % Hout;   t /= Hout;
    int co = t % Cout;   int b = t / Cout;

    float acc = bias[co];
    const float* wp = wt + co * Cin * 9;
    int iy0 = oy * stride - 1;
    int ix0 = ox * stride - 1;
    for (int ci = 0; ci < Cin; ci++) {
        const float* ip = in + ((size_t)(b * Cin + ci) * Hin) * Win;
        const float* wc = wp + ci * 9;
        #pragma unroll
        for (int ky = 0; ky < 3; ky++) {
            int iy = iy0 + ky;
            if (iy < 0 || iy >= Hin) continue;
            const float* irow = ip + (size_t)iy * Win;
            #pragma unroll
            for (int kx = 0; kx < 3; kx++) {
                int ix = ix0 + kx;
                if (ix < 0 || ix >= Win) continue;
                acc += irow[ix] * wc[ky * 3 + kx];
            }
        }
    }
    out[idx] = gelu_tanh(acc);
}

// ---------------- global mean over 7x7 ----------------
__global__ void gmean_kernel(const float* __restrict__ g5, float* __restrict__ gc) {
    int idx = blockIdx.x * blockDim.x + threadIdx.x;   // BQ*64
    if (idx >= BQ * 64) return;
    const float* p = g5 + (size_t)idx * 49;
    float s = 0.f;
    #pragma unroll
    for (int i = 0; i < 49; i++) s += p[i];
    gc[idx] = s / 49.0f;
}

// ---------------- bilinear patch gather + gc broadcast into fused (tf32-rounded) ----------------
__global__ void patch_kernel(const float* __restrict__ points, const float* __restrict__ fmap,
                             const float* __restrict__ gc, float* __restrict__ fused) {
    int p = blockIdx.x * 4 + (threadIdx.x >> 6);
    int t = threadIdx.x & 63;
    int b = p >> 12;
    float px = points[p * 2 + 0];
    float py = points[p * 2 + 1];
    int i = t >> 3, j = t & 7;

    const float step = 2.0f / 55.0f;
    float gx = (px * 2.0f - 1.0f) + ((float)i - 3.5f) * step;
    float gy = (py * 2.0f - 1.0f) + ((float)j - 3.5f) * step;
    float ix = (gx + 1.0f) * 0.5f * 55.0f;
    float iy = (gy + 1.0f) * 0.5f * 55.0f;
    float x0f = floorf(ix), y0f = floorf(iy);
    int x0 = (int)x0f, y0 = (int)y0f;
    int x1 = x0 + 1,  y1 = y0 + 1;
    float wx1 = ix - x0f, wx0 = 1.0f - wx1;
    float wy1 = iy - y0f, wy0 = 1.0f - wy1;

    bool vx0 = (x0 >= 0) && (x0 < FW), vx1 = (x1 >= 0) && (x1 < FW);
    bool vy0 = (y0 >= 0) && (y0 < FW), vy1 = (y1 >= 0) && (y1 < FW);
    int cx0 = min(max(x0, 0), FW - 1), cx1 = min(max(x1, 0), FW - 1);
    int cy0 = min(max(y0, 0), FW - 1), cy1 = min(max(y1, 0), FW - 1);
    float w00 = (vx0 && vy0) ? wx0 * wy0 : 0.f;
    float w10 = (vx1 && vy0) ? wx1 * wy0 : 0.f;
    float w01 = (vx0 && vy1) ? wx0 * wy1 : 0.f;
    float w11 = (vx1 && vy1) ? wx1 * wy1 : 0.f;
    int i00 = cy0 * FW + cx0, i10 = cy0 * FW + cx1;
    int i01 = cy1 * FW + cx0, i11 = cy1 * FW + cx1;

    float* orow = fused + (size_t)p * 576;
    #pragma unroll
    for (int c = 0; c < 4; c++) {
        const float* f = fmap + (size_t)(b * 4 + c) * (FW * FW);
        float v = w00 * f[i00] + w10 * f[i10] + w01 * f[i01] + w11 * f[i11];
        orow[256 + c * 64 + t] = tf32r(v);
    }
    orow[512 + t] = tf32r(gc[b * 64 + t]);
}

// ---------------- tf32 mma.sync GEMM-NT ----------------
// C[m,n] = sum_k A[m,k]*W[n,k] + bias[n] (+gelu, +tf32 round).
// CTA tile 128x128, BK=32, 256 threads = 8 warps, warp tile 64x32 (4x4 m16n8k8 per k8-step).
// Smem layout [128][36] (pad 4): fragment LDS bank = (4*row + k) % 32 -> conflict-free.
#define SMPAD 36
#define STAGE_F (128 * SMPAD)                 // floats per matrix per stage
#define MMA_SMEM_BYTES (4 * STAGE_F * 4 * 2)  // Hmm: computed explicitly below

#define GEMM_SMEM_BYTES (2 /*bufs*/ * 2 /*A,B*/ * STAGE_F * 4)

template<bool DOGELU, bool ROUND>
__global__ void __launch_bounds__(256) mma_gemm(const float* __restrict__ A,
                                                const float* __restrict__ W,
                                                const float* __restrict__ bias,
                                                float* __restrict__ C,
                                                int K, int ldc) {
    extern __shared__ float sm[];
    float* As = sm;                     // [2][128][SMPAD]
    float* Bs = sm + 2 * STAGE_F;       // [2][128][SMPAD]
    const uint32_t uAs = smem_u32(As), uBs = smem_u32(Bs);

    const int tid  = threadIdx.x;
    const int lane = tid & 31, wid = tid >> 5;
    const int wm = wid >> 2, wn = wid & 3;      // 2 x 4 warps, warp tile 64(M) x 32(N)
    const int bm = blockIdx.y << 7, bn = blockIdx.x << 7;

    const int prow = tid >> 1;                   // 0..127
    const int pcol = (tid & 1) << 4;             // 0 or 16 (floats)
    const float* apg = A + (size_t)(bm + prow) * K + pcol;
    const float* wpg = W + (size_t)(bn + prow) * K + pcol;
    const uint32_t sA_off = (uint32_t)(prow * SMPAD + pcol) * 4u;
    const uint32_t sB_off = sA_off;

    const int S = K >> 5;

    // prefetch helper (macro-style lambda)
    auto prefetch = [&](int s, int buf) {
        const float* ap = apg + s * 32;
        const float* wp = wpg + s * 32;
        uint32_t da = uAs + (uint32_t)buf * (STAGE_F * 4u) + sA_off;
        uint32_t db = uBs + (uint32_t)buf * (STAGE_F * 4u) + sB_off;
        #pragma unroll
        for (int q = 0; q < 4; q++)
            asm volatile("cp.async.cg.shared.global [%0], [%1], 16;"
                         :: "r"(da + q * 16u), "l"(ap + q * 4));
        #pragma unroll
        for (int q = 0; q < 4; q++)
            asm volatile("cp.async.cg.shared.global [%0], [%1], 16;"
                         :: "r"(db + q * 16u), "l"(wp + q * 4));
        asm volatile("cp.async.commit_group;" ::: "memory");
    };

    float acc[4][4][4];
    #pragma unroll
    for (int i = 0; i < 4; i++)
        #pragma unroll
        for (int j = 0; j < 4; j++)
            #pragma unroll
            for (int q = 0; q < 4; q++) acc[i][j][q] = 0.f;

    prefetch(0, 0);
    if (S > 1) prefetch(1, 1);

    const int g4 = lane >> 2;          // 0..7
    const int t4 = lane & 3;           // 0..3

    for (int s = 0; s < S; s++) {
        if (s + 1 < S) { asm volatile("cp.async.wait_group 1;" ::: "memory"); }
        else           { asm volatile("cp.async.wait_group 0;" ::: "memory"); }
        __syncthreads();

        const float* as = As + (s & 1) * STAGE_F;
        const float* bs = Bs + (s & 1) * STAGE_F;
        #pragma unroll
        for (int kk = 0; kk < 4; kk++) {
            const int c0 = kk * 8 + t4;
            float ar[4][4];
            #pragma unroll
            for (int mt = 0; mt < 4; mt++) {
                int r = wm * 64 + mt * 16 + g4;
                ar[mt][0] = as[r * SMPAD + c0];
                ar[mt][1] = as[(r + 8) * SMPAD + c0];
                ar[mt][2] = as[r * SMPAD + c0 + 4];
                ar[mt][3] = as[(r + 8) * SMPAD + c0 + 4];
            }
            float br[4][2];
            #pragma unroll
            for (int nt = 0; nt < 4; nt++) {
                int n = wn * 32 + nt * 8 + g4;
                br[nt][0] = bs[n * SMPAD + c0];
                br[nt][1] = bs[n * SMPAD + c0 + 4];
            }
            #pragma unroll
            for (int mt = 0; mt < 4; mt++)
                #pragma unroll
                for (int nt = 0; nt < 4; nt++)
                    mma_tf32(acc[mt][nt], ar[mt], br[nt]);
        }
        __syncthreads();
        if (s + 2 < S) prefetch(s + 2, s & 1);
    }

    // epilogue
    #pragma unroll
    for (int nt = 0; nt < 4; nt++) {
        int col = bn + wn * 32 + nt * 8 + t4 * 2;
        float b0 = bias[col], b1 = bias[col + 1];
        #pragma unroll
        for (int mt = 0; mt < 4; mt++) {
            int row = bm + wm * 64 + mt * 16 + g4;
            float v0 = acc[mt][nt][0] + b0;
            float v1 = acc[mt][nt][1] + b1;
            float v2 = acc[mt][nt][2] + b0;
            float v3 = acc[mt][nt][3] + b1;
            if (DOGELU) { v0 = gelu_tanh(v0); v1 = gelu_tanh(v1); v2 = gelu_tanh(v2); v3 = gelu_tanh(v3); }
            if (ROUND)  { v0 = tf32r(v0); v1 = tf32r(v1); v2 = tf32r(v2); v3 = tf32r(v3); }
            *(float2*)(C + (size_t)row * ldc + col)       = make_float2(v0, v1);
            *(float2*)(C + (size_t)(row + 8) * ldc + col) = make_float2(v2, v3);
        }
    }
}

// ---------------- final GEMV: out[m] = dot(h[m,:512], hw2) + hb2 ----------------
__global__ void gemv_out(const float* __restrict__ h, const float* __restrict__ w2,
                         const float* __restrict__ b2, float* __restrict__ out) {
    int m = blockIdx.x * 8 + (threadIdx.x >> 5);
    int lane = threadIdx.x & 31;
    const float4* hp = (const float4*)(h + (size_t)m * 512);
    const float4* wp = (const float4*)w2;
    float s = 0.f;
    #pragma unroll
    for (int it = 0; it < 4; it++) {
        float4 a = hp[lane + it * 32];
        float4 b = wp[lane + it * 32];
        s += a.x * b.x + a.y * b.y + a.z * b.z + a.w * b.w;
    }
    #pragma unroll
    for (int o = 16; o > 0; o >>= 1) s += __shfl_xor_sync(0xFFFFFFFFu, s, o);
    if (lane == 0) out[m] = s + b2[0];
}

// ---------------- launch ----------------
extern "C" void kernel_launch(void* const* d_in, const int* in_sizes, int n_in,
                              void* d_out, int out_size) {
    const float* points = (const float*)d_in[0];
    const float* images = (const float*)d_in[1];
    const float* pw1 = (const float*)d_in[2];  const float* pb1 = (const float*)d_in[3];
    const float* pw2 = (const float*)d_in[4];  const float* pb2 = (const float*)d_in[5];
    const float* pw3 = (const float*)d_in[6];  const float* pb3 = (const float*)d_in[7];
    const float* gw1 = (const float*)d_in[8];  const float* gb1 = (const float*)d_in[9];
    const float* gw2 = (const float*)d_in[10]; const float* gb2 = (const float*)d_in[11];
    const float* gw3 = (const float*)d_in[12]; const float* gb3 = (const float*)d_in[13];
    const float* gw4 = (const float*)d_in[14]; const float* gb4 = (const float*)d_in[15];
    const float* gw5 = (const float*)d_in[16]; const float* gb5 = (const float*)d_in[17];
    const float* lw1 = (const float*)d_in[18]; const float* lb1 = (const float*)d_in[19];
    const float* lw2 = (const float*)d_in[20]; const float* lb2 = (const float*)d_in[21];
    const float* hw1 = (const float*)d_in[22]; const float* hb1 = (const float*)d_in[23];
    const float* hw2 = (const float*)d_in[24]; const float* hb2 = (const float*)d_in[25];
    float* out = (float*)d_out;

    float *pe, *lw1p, *lw2t, *hw1t, *pf1, *fused, *h;
    float *f1, *f2, *fmap, *g1, *g2, *g3, *g4, *g5, *gc;
    cudaGetSymbolAddress((void**)&pe,    d_pe);
    cudaGetSymbolAddress((void**)&lw1p,  d_lw1p);
    cudaGetSymbolAddress((void**)&lw2t,  d_lw2t);
    cudaGetSymbolAddress((void**)&hw1t,  d_hw1t);
    cudaGetSymbolAddress((void**)&pf1,   d_pf1);
    cudaGetSymbolAddress((void**)&fused, d_fused);
    cudaGetSymbolAddress((void**)&h,     d_h);
    cudaGetSymbolAddress((void**)&f1,    d_f1);
    cudaGetSymbolAddress((void**)&f2,    d_f2);
    cudaGetSymbolAddress((void**)&fmap,  d_fmap);
    cudaGetSymbolAddress((void**)&g1,    d_g1);
    cudaGetSymbolAddress((void**)&g2,    d_g2);
    cudaGetSymbolAddress((void**)&g3,    d_g3);
    cudaGetSymbolAddress((void**)&g4,    d_g4);
    cudaGetSymbolAddress((void**)&g5,    d_g5);
    cudaGetSymbolAddress((void**)&gc,    d_gc);

    cudaFuncSetAttribute(mma_gemm<true, true>,   cudaFuncAttributeMaxDynamicSharedMemorySize, GEMM_SMEM_BYTES);
    cudaFuncSetAttribute(mma_gemm<false, true>,  cudaFuncAttributeMaxDynamicSharedMemorySize, GEMM_SMEM_BYTES);
    cudaFuncSetAttribute(mma_gemm<true, false>,  cudaFuncAttributeMaxDynamicSharedMemorySize, GEMM_SMEM_BYTES);

    const int T = 256;
    auto blocks = [](int total) { return (total + 255) / 256; };

    // inputs prep (tf32-rounded operands)
    embed_kernel<<<blocks(MTOT * 16), T>>>(points, pe);
    pack_lw1<<<blocks(256 * 64), T>>>(lw1, lw1p);
    round_copy<<<blocks(256 * 256), T>>>(lw2, lw2t, 256 * 256);
    round_copy<<<blocks(512 * 576), T>>>(hw1, hw1t, 512 * 576);

    // plane encoder
    int t1 = BQ * 16 * 112 * 112;
    conv3x3_gelu<<<blocks(t1), T>>>(images, pw1, pb1, f1, 3, 16, 224, 224, 112, 112, 2, t1);
    int t2 = BQ * 32 * 56 * 56;
    conv3x3_gelu<<<blocks(t2), T>>>(f1, pw2, pb2, f2, 16, 32, 112, 112, 56, 56, 2, t2);
    int t3 = BQ * 4 * 56 * 56;
    conv3x3_gelu<<<blocks(t3), T>>>(f2, pw3, pb3, fmap, 32, 4, 56, 56, 56, 56, 1, t3);

    // global encoder
    int u1 = BQ * 4 * 112 * 112;
    conv3x3_gelu<<<blocks(u1), T>>>(images, gw1, gb1, g1, 3, 4, 224, 224, 112, 112, 2, u1);
    int u2 = BQ * 8 * 56 * 56;
    conv3x3_gelu<<<blocks(u2), T>>>(g1, gw2, gb2, g2, 4, 8, 112, 112, 56, 56, 2, u2);
    int u3 = BQ * 16 * 28 * 28;
    conv3x3_gelu<<<blocks(u3), T>>>(g2, gw3, gb3, g3, 8, 16, 56, 56, 28, 28, 2, u3);
    int u4 = BQ * 32 * 14 * 14;
    conv3x3_gelu<<<blocks(u4), T>>>(g3, gw4, gb4, g4, 16, 32, 28, 28, 14, 14, 2, u4);
    int u5 = BQ * 64 * 7 * 7;
    conv3x3_gelu<<<blocks(u5), T>>>(g4, gw5, gb5, g5, 32, 64, 14, 14, 7, 7, 2, u5);
    gmean_kernel<<<blocks(BQ * 64), T>>>(g5, gc);

    // point MLP (tf32 tensor cores)
    mma_gemm<true,  true ><<<dim3(2, 512), 256, GEMM_SMEM_BYTES>>>(pe,   lw1p, lb1, pf1,   64,  256);
    mma_gemm<false, true ><<<dim3(2, 512), 256, GEMM_SMEM_BYTES>>>(pf1,  lw2t, lb2, fused, 256, 576);

    // patches + gc into fused[:, 256:576]
    patch_kernel<<<MTOT / 4, 256>>>(points, fmap, gc, fused);

    // head (tf32 tensor cores)
    mma_gemm<true,  false><<<dim3(4, 512), 256, GEMM_SMEM_BYTES>>>(fused, hw1t, hb1, h, 576, 512);

    // out = h @ hw2^T + hb2 (fp32 GEMV)
    gemv_out<<<MTOT / 8, 256>>>(h, hw2, hb2, out);

    (void)in_sizes; (void)n_in; (void)out_size;
}